// round 4
// baseline (speedup 1.0000x reference)
#include <cuda_runtime.h>
#include <cuda_bf16.h>

#define NMAX 100000
#define EMAX 3200000
#define FOUT 64
#define FIN  256

// ---------- device scratch (static; no allocation allowed) ----------
__device__ float g_h[NMAX * FOUT];        // projected features
__device__ float g_asrc[NMAX];
__device__ float g_adst[NMAX];
__device__ int   g_cnt[NMAX];             // in-degree histogram
__device__ int   g_cur[NMAX];             // reorder cursors
__device__ int   g_start[NMAX + 1];       // CSR row offsets (by dst)
__device__ int   g_bsum[256];             // scan block sums
__device__ int2  g_csr[EMAX];             // (src, bits(p)) per edge, grouped by dst

// ---------------- init: zero histogram ----------------
__global__ void k_init(int n) {
    int i = blockIdx.x * blockDim.x + threadIdx.x;
    if (i < n) g_cnt[i] = 0;
}

// ---------------- GEMM: h = x @ W, fused a_src/a_dst epilogue ----------------
// block = 256 threads, 64 nodes/block, k-chunked by 64.
// thread (tf = t%16, tn = t/16) computes 4 nodes x 4 features.
#define XS_STRIDE 68
__global__ __launch_bounds__(256) void k_gemm(
    const float* __restrict__ x, const float* __restrict__ W,
    const float* __restrict__ att_src, const float* __restrict__ att_dst, int n)
{
    __shared__ float ws[64 * 64];          // [k][f]
    __shared__ float xs[64 * XS_STRIDE];   // [k][node], padded

    const int t   = threadIdx.x;
    const int tf  = t & 15;        // feature group: f0 = 4*tf
    const int tn  = t >> 4;        // node group:    n0 = 4*tn
    const int node0 = blockIdx.x * 64;

    float acc[4][4];
#pragma unroll
    for (int i = 0; i < 4; i++)
#pragma unroll
        for (int j = 0; j < 4; j++) acc[i][j] = 0.f;

    const int kk = t & 63;         // for x loads
    for (int kc = 0; kc < 4; kc++) {
        const int k0 = kc * 64;
        // load W[k0:k0+64][0:64]
#pragma unroll
        for (int i = t; i < 4096; i += 256) ws[i] = W[k0 * 64 + i];
        // load x tile transposed: xs[k][node]
#pragma unroll
        for (int nn = (t >> 6); nn < 64; nn += 4) {
            int node = node0 + nn;
            float v = (node < n) ? x[node * FIN + k0 + kk] : 0.f;
            xs[kk * XS_STRIDE + nn] = v;
        }
        __syncthreads();
#pragma unroll 8
        for (int k = 0; k < 64; k++) {
            const float4 wv = *(const float4*)(ws + k * 64 + (tf << 2));
            const float4 xv = *(const float4*)(xs + k * XS_STRIDE + (tn << 2));
            acc[0][0] += xv.x * wv.x; acc[0][1] += xv.x * wv.y;
            acc[0][2] += xv.x * wv.z; acc[0][3] += xv.x * wv.w;
            acc[1][0] += xv.y * wv.x; acc[1][1] += xv.y * wv.y;
            acc[1][2] += xv.y * wv.z; acc[1][3] += xv.y * wv.w;
            acc[2][0] += xv.z * wv.x; acc[2][1] += xv.z * wv.y;
            acc[2][2] += xv.z * wv.z; acc[2][3] += xv.z * wv.w;
            acc[3][0] += xv.w * wv.x; acc[3][1] += xv.w * wv.y;
            acc[3][2] += xv.w * wv.z; acc[3][3] += xv.w * wv.w;
        }
        __syncthreads();
    }

    // epilogue: store h, reduce a_src/a_dst across the 16 feature-lanes
    const int f0 = tf << 2;
    float as0 = att_src[f0], as1 = att_src[f0 + 1], as2 = att_src[f0 + 2], as3 = att_src[f0 + 3];
    float ad0 = att_dst[f0], ad1 = att_dst[f0 + 1], ad2 = att_dst[f0 + 2], ad3 = att_dst[f0 + 3];

#pragma unroll
    for (int i = 0; i < 4; i++) {
        int node = node0 + (tn << 2) + i;
        float4 hv = make_float4(acc[i][0], acc[i][1], acc[i][2], acc[i][3]);
        float ps = hv.x * as0 + hv.y * as1 + hv.z * as2 + hv.w * as3;
        float pd = hv.x * ad0 + hv.y * ad1 + hv.z * ad2 + hv.w * ad3;
#pragma unroll
        for (int off = 1; off < 16; off <<= 1) {
            ps += __shfl_xor_sync(0xffffffffu, ps, off);
            pd += __shfl_xor_sync(0xffffffffu, pd, off);
        }
        if (node < n) {
            *(float4*)(g_h + node * FOUT + f0) = hv;
            if (tf == 0) { g_asrc[node] = ps; g_adst[node] = pd; }
        }
    }
}

// ---------------- count in-degrees ----------------
__global__ void k_count(const int* __restrict__ dst, int e) {
    int i = blockIdx.x * blockDim.x + threadIdx.x;
    if (i < e) atomicAdd(&g_cnt[dst[i]], 1);
}

// ---------------- scan (3-phase exclusive prefix sum of g_cnt -> g_start) ----
__global__ void k_scanA(int n) {
    __shared__ int sm[256];
    const int t = threadIdx.x;
    const int base = blockIdx.x * 1024;
    const int i0 = base + t * 4;
    int v[4];
#pragma unroll
    for (int j = 0; j < 4; j++) v[j] = (i0 + j < n) ? g_cnt[i0 + j] : 0;
    int s = v[0] + v[1] + v[2] + v[3];
    sm[t] = s;
    __syncthreads();
#pragma unroll
    for (int off = 1; off < 256; off <<= 1) {
        int xv = (t >= off) ? sm[t - off] : 0;
        __syncthreads();
        sm[t] += xv;
        __syncthreads();
    }
    int run = sm[t] - s;  // exclusive prefix of this thread within block
#pragma unroll
    for (int j = 0; j < 4; j++) {
        if (i0 + j < n) g_start[i0 + j] = run;
        run += v[j];
    }
    if (t == 255) g_bsum[blockIdx.x] = sm[255];
}

__global__ void k_scanB(int nb, int n) {
    if (threadIdx.x == 0) {
        int run = 0;
        for (int i = 0; i < nb; i++) { int v = g_bsum[i]; g_bsum[i] = run; run += v; }
        g_start[n] = run;   // == E
    }
}

__global__ void k_scanC(int n) {
    int i = blockIdx.x * blockDim.x + threadIdx.x;
    if (i < n) {
        g_start[i] += g_bsum[i >> 10];
        g_cur[i] = 0;
    }
}

// ---------------- reorder edges into CSR, precompute p = exp(leakyrelu(e)) ----
__global__ void k_reorder(const int* __restrict__ src, const int* __restrict__ dst, int e) {
    int i = blockIdx.x * blockDim.x + threadIdx.x;
    if (i >= e) return;
    int s = src[i];
    int d = dst[i];
    int pos = atomicAdd(&g_cur[d], 1);
    int idx = g_start[d] + pos;
    float l = g_asrc[s] + g_adst[d];
    l = l > 0.f ? l : 0.2f * l;
    float p = __expf(l);
    g_csr[idx] = make_int2(s, __float_as_int(p));
}

// ---------------- aggregate: warp per destination node, no atomics ----------
__global__ __launch_bounds__(256) void k_agg(
    const float* __restrict__ bias, float* __restrict__ out, int n)
{
    const int warp = (blockIdx.x * blockDim.x + threadIdx.x) >> 5;
    const int lane = threadIdx.x & 31;
    if (warp >= n) return;
    const int d = warp;
    int e  = g_start[d];
    const int e1 = g_start[d + 1];

    float acc0 = 0.f, acc1 = 0.f, den = 0.f;

    for (; e + 4 <= e1; e += 4) {
        int2 sp0 = g_csr[e], sp1 = g_csr[e + 1], sp2 = g_csr[e + 2], sp3 = g_csr[e + 3];
        float p0 = __int_as_float(sp0.y), p1 = __int_as_float(sp1.y);
        float p2 = __int_as_float(sp2.y), p3 = __int_as_float(sp3.y);
        const float* h0 = g_h + (size_t)sp0.x * FOUT;
        const float* h1 = g_h + (size_t)sp1.x * FOUT;
        const float* h2 = g_h + (size_t)sp2.x * FOUT;
        const float* h3 = g_h + (size_t)sp3.x * FOUT;
        float a0 = h0[lane], b0 = h0[lane + 32];
        float a1 = h1[lane], b1 = h1[lane + 32];
        float a2 = h2[lane], b2 = h2[lane + 32];
        float a3 = h3[lane], b3 = h3[lane + 32];
        acc0 += p0 * a0; acc1 += p0 * b0;
        acc0 += p1 * a1; acc1 += p1 * b1;
        acc0 += p2 * a2; acc1 += p2 * b2;
        acc0 += p3 * a3; acc1 += p3 * b3;
        den += p0 + p1 + p2 + p3;
    }
    for (; e < e1; e++) {
        int2 sp = g_csr[e];
        float p = __int_as_float(sp.y);
        const float* hp = g_h + (size_t)sp.x * FOUT;
        acc0 += p * hp[lane];
        acc1 += p * hp[lane + 32];
        den += p;
    }

    // self loop
    float l = g_asrc[d] + g_adst[d];
    l = l > 0.f ? l : 0.2f * l;
    float ps = __expf(l);
    const float* hd = g_h + (size_t)d * FOUT;
    acc0 += ps * hd[lane];
    acc1 += ps * hd[lane + 32];
    den  += ps;

    float inv = 1.0f / (den + 1e-16f);
    out[d * FOUT + lane]      = acc0 * inv + bias[lane];
    out[d * FOUT + lane + 32] = acc1 * inv + bias[lane + 32];
}

// ---------------- launch ----------------
extern "C" void kernel_launch(void* const* d_in, const int* in_sizes, int n_in,
                              void* d_out, int out_size)
{
    const float* x        = (const float*)d_in[0];
    const int*   ei       = (const int*)d_in[1];
    const float* W        = (const float*)d_in[2];
    const float* att_src  = (const float*)d_in[3];
    const float* att_dst  = (const float*)d_in[4];
    const float* bias     = (const float*)d_in[5];
    float* out = (float*)d_out;

    const int n = in_sizes[0] / FIN;
    const int e = in_sizes[1] / 2;
    const int* src = ei;
    const int* dst = ei + e;

    k_init<<<(n + 255) / 256, 256>>>(n);
    k_gemm<<<(n + 63) / 64, 256>>>(x, W, att_src, att_dst, n);
    k_count<<<(e + 255) / 256, 256>>>(dst, e);
    const int nb = (n + 1023) / 1024;
    k_scanA<<<nb, 256>>>(n);
    k_scanB<<<1, 32>>>(nb, n);
    k_scanC<<<(n + 255) / 256, 256>>>(n);
    k_reorder<<<(e + 255) / 256, 256>>>(src, dst, e);
    k_agg<<<(n * 32 + 255) / 256, 256>>>(bias, out, n);
}